// round 17
// baseline (speedup 1.0000x reference)
#include <cuda_runtime.h>

// BallPointQuery: B=4, N=16384, M=2048, radius 0.2, MAX_SAMPLES=64.
// Output float32 [B, M, 64]: ascending in-ball point indices, padded with the
// first found index (N if none found).
//
// Pipeline:
//  1. repack: (x,y,z) -> float4(x,y,z,p2); also zeros the phase-2 worklist ctr
//  2. phase1: one warp per centroid scans points [0, N/2) with early exit.
//     Centroids with <64 hits are pushed to a worklist (~2-4% of centroids).
//  3. phase2: finishes [N/2, N) for worklist centroids only, then pads.

#define BQ_B 4
#define BQ_N 16384
#define BQ_HALF (BQ_N / 2)
#define BQ_M 2048
#define BQ_MAXS 64
#define BQ_R2 0.04f
#define BQ_UNROLL 8

__device__ float4 g_pts[BQ_B * BQ_N];        // 1 MB
__device__ int    g_wl_count;
__device__ int    g_worklist[BQ_B * BQ_M];   // packed (w << 7) | cnt

__global__ __launch_bounds__(256) void repack_kernel(const float* __restrict__ pcs)
{
    const int i = blockIdx.x * blockDim.x + threadIdx.x;
    if (i == 0) g_wl_count = 0;   // re-zeroed every launch (graph replay safe)
    if (i < BQ_B * BQ_N) {
        const float px = pcs[i * 3 + 0];
        const float py = pcs[i * 3 + 1];
        const float pz = pcs[i * 3 + 2];
        const float p2 = px * px + py * py + pz * pz;
        g_pts[i] = make_float4(px, py, pz, p2);
    }
}

// Scan [lo, hi) appending hits at o[cnt..]; returns updated cnt. Warp-collective.
__device__ __forceinline__ int scan_range(
    const float4* __restrict__ pb, float* __restrict__ o,
    float cx, float cy, float cz, float c2,
    int lo, int hi, int cnt, int lane)
{
    const unsigned lt = (1u << lane) - 1u;
    #pragma unroll 1
    for (int base = lo; base < hi; base += 32 * BQ_UNROLL) {
        float d2v[BQ_UNROLL];
        #pragma unroll
        for (int g = 0; g < BQ_UNROLL; g++) {
            const float4 p = pb[base + g * 32 + lane];
            const float dot = cx * p.x + cy * p.y + cz * p.z;
            d2v[g] = c2 + p.w - 2.0f * dot;   // same numeric form as R13-R15
        }
        #pragma unroll
        for (int g = 0; g < BQ_UNROLL; g++) {
            const bool hit = (d2v[g] <= BQ_R2);
            const unsigned mask = __ballot_sync(0xffffffffu, hit);
            if (hit) {
                const int pos = cnt + __popc(mask & lt);
                if (pos < BQ_MAXS) o[pos] = (float)(base + g * 32 + lane);
            }
            cnt += __popc(mask);
        }
        if (cnt >= BQ_MAXS) break;  // warp-uniform
    }
    return cnt;
}

__global__ void ball_query_phase1(
    const float* __restrict__ centroids,  // [B, M, 3]
    float* __restrict__ out)              // [B, M, MAXS]
{
    const int w = blockIdx.x * (blockDim.x >> 5) + (threadIdx.x >> 5);
    const int lane = threadIdx.x & 31;
    if (w >= BQ_B * BQ_M) return;

    const int b = w / BQ_M;
    const float* c = centroids + (size_t)w * 3;
    const float cx = c[0], cy = c[1], cz = c[2];
    const float c2 = cx * cx + cy * cy + cz * cz;

    const float4* pb = g_pts + (size_t)b * BQ_N;
    float* o = out + (size_t)w * BQ_MAXS;

    int cnt = scan_range(pb, o, cx, cy, cz, c2, 0, BQ_HALF, 0, lane);

    if (cnt < BQ_MAXS) {
        if (lane == 0) {
            const int slot = atomicAdd(&g_wl_count, 1);
            g_worklist[slot] = (w << 7) | cnt;
        }
    }
}

__global__ void ball_query_phase2(
    const float* __restrict__ centroids,
    float* __restrict__ out)
{
    const int j = blockIdx.x * (blockDim.x >> 5) + (threadIdx.x >> 5);
    const int lane = threadIdx.x & 31;
    if (j >= g_wl_count) return;

    const int e = g_worklist[j];
    const int w = e >> 7;
    int cnt = e & 127;

    const int b = w / BQ_M;
    const float* c = centroids + (size_t)w * 3;
    const float cx = c[0], cy = c[1], cz = c[2];
    const float c2 = cx * cx + cy * cy + cz * cz;

    const float4* pb = g_pts + (size_t)b * BQ_N;
    float* o = out + (size_t)w * BQ_MAXS;

    cnt = scan_range(pb, o, cx, cy, cz, c2, BQ_HALF, BQ_N, cnt, lane);

    if (cnt < BQ_MAXS) {
        const float fv = (cnt > 0) ? o[0] : (float)BQ_N;
        for (int pos = cnt + lane; pos < BQ_MAXS; pos += 32) {
            o[pos] = fv;
        }
    }
}

extern "C" void kernel_launch(void* const* d_in, const int* in_sizes, int n_in,
                              void* d_out, int out_size)
{
    const float* pcs       = (const float*)d_in[0];  // 196608 floats
    const float* centroids = (const float*)d_in[1];  // 24576 floats
    float* out             = (float*)d_out;          // 524288 float32

    const int npts = BQ_B * BQ_N;                    // 65536
    repack_kernel<<<(npts + 255) / 256, 256>>>(pcs);

    const int total_warps = BQ_B * BQ_M;             // 8192
    const int threads = 128;                          // 4 warps/block (fine balance)
    const int blocks = (total_warps * 32 + threads - 1) / threads;  // 2048
    ball_query_phase1<<<blocks, threads>>>(centroids, out);
    ball_query_phase2<<<blocks, threads>>>(centroids, out);
}